// round 13
// baseline (speedup 1.0000x reference)
#include <cuda_runtime.h>
#include <cuda_bf16.h>
#include <cstdint>
#include <math.h>

#define C_DIM   512
#define HW      4096
#define BATCH   2
#define NGROUPS 32
#define CPG     16
#define EPS     1e-5f

// ---------------- scratch (device globals; allocations forbidden) -----------
__device__ __align__(16) __nv_bfloat16 g_hT [(size_t)BATCH * HW * C_DIM];      // (b, n, c)
__device__ __align__(16) __nv_bfloat16 g_qkT[(size_t)BATCH * HW * 2 * C_DIM];  // (b, n, 1024) q|k
__device__ __align__(16) __nv_bfloat16 g_v  [(size_t)BATCH * C_DIM * HW];      // (b, c, n)
__device__ __align__(16) __nv_bfloat16 g_oT [(size_t)BATCH * HW * C_DIM];      // (b, n, c)
__device__ __align__(16) __nv_bfloat16 g_es [(size_t)BATCH * HW * HW];         // exp(scores)
__device__ __align__(16) __nv_bfloat16 g_wb [4 * C_DIM * C_DIM];               // bf16 weights
__device__ float g_bqk[2 * C_DIM];
__device__ float g_rowsum[BATCH * HW];
__device__ float g_stats[BATCH * NGROUPS * 2];

// ---------------- helpers ----------------------------------------------------
__device__ __forceinline__ uint32_t smem_u32(const void* p) {
    uint32_t a;
    asm("{ .reg .u64 t; cvta.to.shared.u64 t, %1; cvt.u32.u64 %0, t; }"
        : "=r"(a) : "l"(p));
    return a;
}
#define SMEM_SWIZZLE_128B(off) ((off) ^ (((off) >> 3) & 0x70))

__device__ __forceinline__ void cp_async16(uint32_t saddr, const void* g) {
    asm volatile("cp.async.cg.shared.global [%0], [%1], 16;"
                 :: "r"(saddr), "l"(g) : "memory");
}
#define CP_COMMIT() asm volatile("cp.async.commit_group;" ::: "memory")
#define CP_WAIT1()  asm volatile("cp.async.wait_group 1;" ::: "memory")

__device__ __forceinline__ void ldm_x4(uint32_t* r, uint32_t addr) {
    asm volatile("ldmatrix.sync.aligned.m8n8.x4.shared.b16 {%0,%1,%2,%3}, [%4];"
                 : "=r"(r[0]), "=r"(r[1]), "=r"(r[2]), "=r"(r[3]) : "r"(addr));
}
__device__ __forceinline__ void mma_bf16(float* d, const uint32_t* a, const uint32_t* b) {
    asm volatile("mma.sync.aligned.m16n8k16.row.col.f32.bf16.bf16.f32 "
                 "{%0,%1,%2,%3}, {%4,%5,%6,%7}, {%8,%9}, {%0,%1,%2,%3};"
                 : "+f"(d[0]), "+f"(d[1]), "+f"(d[2]), "+f"(d[3])
                 : "r"(a[0]), "r"(a[1]), "r"(a[2]), "r"(a[3]),
                   "r"(b[0]), "r"(b[1]));
}

// ---------------- fused: GroupNorm stats (blocks 0..63) + prep (64..127) ------
__global__ void prep_stats(const float* __restrict__ x, float* __restrict__ stats,
                           const float* __restrict__ wq, const float* __restrict__ wk,
                           const float* __restrict__ wv, const float* __restrict__ wo,
                           const float* __restrict__ bq, const float* __restrict__ bk,
                           __nv_bfloat16* __restrict__ wb, float* __restrict__ bqk,
                           float* __restrict__ rowsum)
{
    const int tid = threadIdx.x;
    if (blockIdx.x < BATCH * NGROUPS) {
        const int bg = blockIdx.x;
        const size_t base = (size_t)bg * CPG * HW;
        const float4* xv = (const float4*)(x + base);
        const int NV = CPG * HW / 4;

        float s = 0.f, ss = 0.f;
        for (int i = tid; i < NV; i += 256) {
            float4 v = xv[i];
            s  += v.x + v.y + v.z + v.w;
            ss += v.x * v.x + v.y * v.y + v.z * v.z + v.w * v.w;
        }
        __shared__ float r1[256], r2[256];
        r1[tid] = s; r2[tid] = ss;
        __syncthreads();
        for (int o = 128; o > 0; o >>= 1) {
            if (tid < o) { r1[tid] += r1[tid + o]; r2[tid] += r2[tid + o]; }
            __syncthreads();
        }
        if (tid == 0) {
            const float inv_n = 1.0f / (float)(CPG * HW);
            float mu  = r1[0] * inv_n;
            float var = r2[0] * inv_n - mu * mu;
            stats[bg * 2 + 0] = mu;
            stats[bg * 2 + 1] = rsqrtf(var + EPS);
        }
    } else {
        const int CC = C_DIM * C_DIM;
        const int pid = (blockIdx.x - BATCH * NGROUPS) * 256 + tid;
        const int nt = 64 * 256;
        __nv_bfloat162* w2 = (__nv_bfloat162*)wb;
        for (int j = pid; j < CC / 2; j += nt) {
            float2 a;
            a = ((const float2*)wq)[j]; w2[j]          = __floats2bfloat162_rn(a.x, a.y);
            a = ((const float2*)wk)[j]; w2[CC/2 + j]   = __floats2bfloat162_rn(a.x, a.y);
            a = ((const float2*)wv)[j]; w2[CC + j]     = __floats2bfloat162_rn(a.x, a.y);
            a = ((const float2*)wo)[j]; w2[3*CC/2 + j] = __floats2bfloat162_rn(a.x, a.y);
        }
        if (pid < C_DIM) { bqk[pid] = bq[pid]; bqk[C_DIM + pid] = bk[pid]; }
        for (int j = pid; j < BATCH * HW; j += nt) rowsum[j] = 0.f;
    }
}

// ---------------- GroupNorm apply + transpose to (n, c) bf16 ------------------
__global__ void gn_apply_t(const float* __restrict__ x,
                           const float* __restrict__ gamma,
                           const float* __restrict__ beta,
                           const float* __restrict__ stats,
                           __nv_bfloat16* __restrict__ hT)
{
    __shared__ float s[64][65];
    const int b  = blockIdx.z;
    const int c0 = blockIdx.y * 64;
    const int n0 = blockIdx.x * 64;
    const int t  = threadIdx.x;
    const int j  = t & 63;
    const int i4 = t >> 6;

#pragma unroll 4
    for (int r = 0; r < 16; r++) {
        const int cl = i4 * 16 + r;
        const int c  = c0 + cl;
        const int g  = c >> 4;
        const float mu   = stats[(b * NGROUPS + g) * 2 + 0];
        const float rinv = stats[(b * NGROUPS + g) * 2 + 1];
        const float ga = gamma[c] * rinv;
        const float be = beta[c] - mu * ga;
        float v = x[((size_t)b * C_DIM + c) * HW + n0 + j];
        s[cl][j] = v * ga + be;
    }
    __syncthreads();
#pragma unroll 4
    for (int r = 0; r < 16; r++) {
        const int nl = i4 * 16 + r;
        hT[((size_t)b * HW + n0 + nl) * C_DIM + c0 + j] = __float2bfloat16(s[j][nl]);
    }
}

// ---------------- bf16 mma.sync GEMM ------------------------------------------
// D(m,n) = epi( sum_k A(m,k) * B(n,k) ); A: rows of ldA, B: rows of ldB.
// Block 128x256, 512 threads (16 warps of 64x32), k-tile 64, 3-stage pipeline.
// Per-thread registers unchanged vs 128x128/256thr; smem amplification 3x -> 2x.
enum { E_QK = 0, E_V = 1, E_EXP = 2, E_AV = 3, E_FIN = 4 };

#define A_TILE  16384              // 128 rows x 128 bytes
#define B_TILE  32768              // 256 rows x 128 bytes
#define NSTAGE  3
#define B_BASE  (NSTAGE * A_TILE)  // 49152
#define SMEM_BYTES (NSTAGE * (A_TILE + B_TILE))   // 147456 -> 1 CTA/SM, 16 warps

// ITERS = rows/64 for 512 threads (each thread: one 16B chunk per iter)
template<int ITERS>
__device__ __forceinline__ void load_tile_async(const __nv_bfloat16* __restrict__ g,
                                                int row0, int k0, int ld,
                                                uint32_t sdst, int t)
{
    const char* base = (const char*)(g + (size_t)row0 * ld + k0);
#pragma unroll
    for (int i = 0; i < ITERS; i++) {
        int idx = i * 512 + t;
        int r   = idx >> 3;
        int c16 = idx & 7;
        const char* src = base + (size_t)r * ld * 2 + c16 * 16;
        uint32_t so = SMEM_SWIZZLE_128B((uint32_t)(r * 128 + c16 * 16));
        cp_async16(sdst + so, src);
    }
}

template<int EPI>
__global__ void __launch_bounds__(512, 1) gemm_mma(
    const __nv_bfloat16* __restrict__ A, const __nv_bfloat16* __restrict__ B,
    void* __restrict__ Cv, const float* __restrict__ bias,
    float* __restrict__ rowsum, const float* __restrict__ resid,
    int M, int N, int K, int ldA, int ldB,
    long sA, long sB, long sC, float alpha)
{
    extern __shared__ char smem[];
    const uint32_t sb = smem_u32(smem);
    const int t = threadIdx.x, lane = t & 31, wid = t >> 5;
    const int wm = wid >> 3;            // 0..1 : 64-row slab
    const int wn = wid & 7;             // 0..7 : 32-col slab
    const int bz = blockIdx.z;
    A += (size_t)bz * sA;
    B += (size_t)bz * sB;
    if (EPI == E_EXP || EPI == E_AV) rowsum += (size_t)bz * HW;
    const int m0 = blockIdx.y * 128;
    const int n0 = blockIdx.x * 256;

    float acc[4][4][4] = {};

    const int NC = K >> 6;
    // prologue: stages 0 and 1 in flight
    load_tile_async<2>(A, m0, 0, ldA, sb, t);
    load_tile_async<4>(B, n0, 0, ldB, sb + B_BASE, t);
    CP_COMMIT();
    load_tile_async<2>(A, m0, 64, ldA, sb + A_TILE, t);
    load_tile_async<4>(B, n0, 64, ldB, sb + B_BASE + B_TILE, t);
    CP_COMMIT();

    // lane-constant address components
    const uint32_t a_r = (uint32_t)(wm * 64 + (lane & 15));
    const uint32_t a_c = (uint32_t)((lane >> 4) * 16);          // bytes
    const uint32_t b_r = (uint32_t)(wn * 32 + (lane & 7) + ((lane >> 4) & 1) * 8);
    const uint32_t b_c = (uint32_t)(((lane >> 3) & 1) * 16);    // bytes

    for (int c = 0; c < NC; c++) {
        CP_WAIT1();
        __syncthreads();

        // issue loads for stage c+2 AFTER the barrier (slot last read at iter c-1)
        if (c + 2 < NC) {
            const int st = (c + 2) % NSTAGE;
            load_tile_async<2>(A, m0, (c + 2) * 64, ldA, sb + st * A_TILE, t);
            load_tile_async<4>(B, n0, (c + 2) * 64, ldB, sb + B_BASE + st * B_TILE, t);
        }
        CP_COMMIT();   // commit every iter (possibly empty) to keep accounting aligned

        const uint32_t abuf = sb + (c % NSTAGE) * A_TILE;
        const uint32_t bbuf = sb + B_BASE + (c % NSTAGE) * B_TILE;
#pragma unroll
        for (int ks = 0; ks < 4; ks++) {
            uint32_t af[4][4];
#pragma unroll
            for (int tm = 0; tm < 4; tm++) {
                uint32_t off = (a_r + tm * 16) * 128 + (uint32_t)(ks * 32) + a_c;
                ldm_x4(af[tm], abuf + SMEM_SWIZZLE_128B(off));
            }
            uint32_t bf[4][2];
#pragma unroll
            for (int p = 0; p < 2; p++) {
                uint32_t r4[4];
                uint32_t off = (b_r + p * 16) * 128 + (uint32_t)(ks * 32) + b_c;
                ldm_x4(r4, bbuf + SMEM_SWIZZLE_128B(off));
                bf[2 * p][0] = r4[0]; bf[2 * p][1] = r4[1];
                bf[2 * p + 1][0] = r4[2]; bf[2 * p + 1][1] = r4[3];
            }
#pragma unroll
            for (int tm = 0; tm < 4; tm++)
#pragma unroll
                for (int tn = 0; tn < 4; tn++)
                    mma_bf16(acc[tm][tn], af[tm], bf[tn]);
        }
    }

    // ---------------- epilogue ----------------
    const int gq = lane >> 2, tq = lane & 3;
#pragma unroll
    for (int tm = 0; tm < 4; tm++) {
#pragma unroll
        for (int h = 0; h < 2; h++) {
            const int m = m0 + wm * 64 + tm * 16 + gq + h * 8;
            float rowadd = 0.f;
            float pm = 0.f;
            if (EPI == E_V || EPI == E_FIN) pm = bias[m];
            if (EPI == E_AV) pm = 1.0f / rowsum[m];
#pragma unroll
            for (int tn = 0; tn < 4; tn++) {
                const int n = n0 + wn * 32 + tn * 8 + tq * 2;
                float d0 = acc[tm][tn][h * 2 + 0];
                float d1 = acc[tm][tn][h * 2 + 1];
                if (EPI == E_QK) { d0 += bias[n]; d1 += bias[n + 1]; }
                if (EPI == E_V)  { d0 += pm; d1 += pm; }
                if (EPI == E_EXP) {
                    d0 = __expf(d0 * alpha);
                    d1 = __expf(d1 * alpha);
                    rowadd += d0 + d1;
                }
                if (EPI == E_AV) { d0 *= pm; d1 *= pm; }
                if (EPI == E_FIN) {
                    const float2 rr = *(const float2*)(resid + (size_t)bz * sC + (size_t)m * N + n);
                    float2 o = make_float2(d0 + pm + rr.x, d1 + pm + rr.y);
                    *(float2*)((float*)Cv + (size_t)bz * sC + (size_t)m * N + n) = o;
                } else {
                    __nv_bfloat162 p2 = __floats2bfloat162_rn(d0, d1);
                    *(__nv_bfloat162*)((__nv_bfloat16*)Cv + (size_t)bz * sC + (size_t)m * N + n) = p2;
                }
            }
            if (EPI == E_EXP) {
                rowadd += __shfl_xor_sync(0xffffffff, rowadd, 1);
                rowadd += __shfl_xor_sync(0xffffffff, rowadd, 2);
                if (tq == 0) atomicAdd(&rowsum[m], rowadd);
            }
        }
    }
}

// ---------------- launch -------------------------------------------------------
extern "C" void kernel_launch(void* const* d_in, const int* in_sizes, int n_in,
                              void* d_out, int out_size)
{
    const float* x    = (const float*)d_in[0];
    const float* gn_w = (const float*)d_in[1];
    const float* gn_b = (const float*)d_in[2];
    const float* wq   = (const float*)d_in[3];
    const float* bq   = (const float*)d_in[4];
    const float* wk   = (const float*)d_in[5];
    const float* bk   = (const float*)d_in[6];
    const float* wv   = (const float*)d_in[7];
    const float* bv   = (const float*)d_in[8];
    const float* wo   = (const float*)d_in[9];
    const float* bo   = (const float*)d_in[10];
    float* out = (float*)d_out;

    __nv_bfloat16 *hT, *qkT, *v, *oT, *es, *wb;
    float *rowsum, *stats, *bqk;
    cudaGetSymbolAddress((void**)&hT,  g_hT);
    cudaGetSymbolAddress((void**)&qkT, g_qkT);
    cudaGetSymbolAddress((void**)&v,   g_v);
    cudaGetSymbolAddress((void**)&oT,  g_oT);
    cudaGetSymbolAddress((void**)&es,  g_es);
    cudaGetSymbolAddress((void**)&wb,  g_wb);
    cudaGetSymbolAddress((void**)&rowsum, g_rowsum);
    cudaGetSymbolAddress((void**)&stats,  g_stats);
    cudaGetSymbolAddress((void**)&bqk,    g_bqk);

    cudaFuncSetAttribute(gemm_mma<E_QK>,  cudaFuncAttributeMaxDynamicSharedMemorySize, SMEM_BYTES);
    cudaFuncSetAttribute(gemm_mma<E_V>,   cudaFuncAttributeMaxDynamicSharedMemorySize, SMEM_BYTES);
    cudaFuncSetAttribute(gemm_mma<E_EXP>, cudaFuncAttributeMaxDynamicSharedMemorySize, SMEM_BYTES);
    cudaFuncSetAttribute(gemm_mma<E_AV>,  cudaFuncAttributeMaxDynamicSharedMemorySize, SMEM_BYTES);
    cudaFuncSetAttribute(gemm_mma<E_FIN>, cudaFuncAttributeMaxDynamicSharedMemorySize, SMEM_BYTES);

    const long NC_  = (long)HW * C_DIM;        // hT / v / oT per-batch stride
    const long NC2_ = (long)HW * 2 * C_DIM;    // qkT per-batch stride
    const long CN_  = (long)C_DIM * HW;
    const long NN_  = (long)HW * HW;
    const int  CC   = C_DIM * C_DIM;
    const float scale = 0.044194173824159216f; // 512^-0.5

    // fused GroupNorm stats + weight/bias/rowsum prep, then GN apply -> hT
    prep_stats<<<128, 256>>>(x, stats, wq, wk, wv, wo, bq, bk, wb, bqk, rowsum);
    gn_apply_t<<<dim3(HW / 64, C_DIM / 64, BATCH), 256>>>(x, gn_w, gn_b, stats, hT);

    // qkT(n, 0:1024) = hT(n,:) . [Wq;Wk](c,:) + bqk[c]   (M=HW, N=1024, K=512)
    gemm_mma<E_QK><<<dim3(4, 32, BATCH), 512, SMEM_BYTES>>>(
        hT, wb, qkT, bqk, nullptr, nullptr,
        HW, 2 * C_DIM, C_DIM, C_DIM, C_DIM, NC_, 0, NC2_, 0.f);

    // v(c,n) = Wv(c,:) . hT(n,:) + bv[c]   (M=C, N=HW, K=C)
    gemm_mma<E_V><<<dim3(16, 4, BATCH), 512, SMEM_BYTES>>>(
        wb + 2 * CC, hT, v, bv, nullptr, nullptr,
        C_DIM, HW, C_DIM, C_DIM, C_DIM, 0, NC_, CN_, 0.f);

    // es(nq,nk) = exp(q(nq,:) . k(nk,:) * scale); rowsum accumulated
    gemm_mma<E_EXP><<<dim3(16, 32, BATCH), 512, SMEM_BYTES>>>(
        qkT, qkT + C_DIM, es, nullptr, rowsum, nullptr,
        HW, HW, C_DIM, 2 * C_DIM, 2 * C_DIM, NC2_, NC2_, NN_, scale);

    // oT(nq,c) = (es(nq,:) . v(c,:)) / rowsum[nq]   (M=HW, N=C, K=HW)
    gemm_mma<E_AV><<<dim3(2, 32, BATCH), 512, SMEM_BYTES>>>(
        es, v, oT, nullptr, rowsum, nullptr,
        HW, C_DIM, HW, HW, HW, NN_, CN_, NC_, 0.f);

    // out(c,n) = Wo(c,:) . oT(n,:) + bo[c] + x(c,n)   (M=C, N=HW, K=C)
    gemm_mma<E_FIN><<<dim3(16, 4, BATCH), 512, SMEM_BYTES>>>(
        wb + 3 * CC, oT, out, bo, nullptr, x,
        C_DIM, HW, C_DIM, C_DIM, C_DIM, 0, NC_, CN_, 0.f);
}

// round 14
// speedup vs baseline: 1.0370x; 1.0370x over previous
#include <cuda_runtime.h>
#include <cuda_bf16.h>
#include <cstdint>
#include <math.h>

#define C_DIM   512
#define HW      4096
#define BATCH   2
#define NGROUPS 32
#define CPG     16
#define EPS     1e-5f

// ---------------- scratch (device globals; allocations forbidden) -----------
__device__ __align__(16) __nv_bfloat16 g_hT [(size_t)BATCH * HW * C_DIM];      // (b, n, c)
__device__ __align__(16) __nv_bfloat16 g_qkT[(size_t)BATCH * HW * 2 * C_DIM];  // (b, n, 1024) q|k
__device__ __align__(16) __nv_bfloat16 g_v  [(size_t)BATCH * C_DIM * HW];      // (b, c, n)
__device__ __align__(16) __nv_bfloat16 g_oT [(size_t)BATCH * HW * C_DIM];      // (b, n, c)
__device__ __align__(16) __nv_bfloat16 g_es [(size_t)BATCH * HW * HW];         // exp(scores)
__device__ __align__(16) __nv_bfloat16 g_wb [4 * C_DIM * C_DIM];               // bf16 weights
__device__ float g_bqk[2 * C_DIM];
__device__ float g_rowsum[BATCH * HW];
__device__ float g_stats[BATCH * NGROUPS * 2];

// ---------------- helpers ----------------------------------------------------
__device__ __forceinline__ uint32_t smem_u32(const void* p) {
    uint32_t a;
    asm("{ .reg .u64 t; cvta.to.shared.u64 t, %1; cvt.u32.u64 %0, t; }"
        : "=r"(a) : "l"(p));
    return a;
}
#define SMEM_SWIZZLE_128B(off) ((off) ^ (((off) >> 3) & 0x70))

__device__ __forceinline__ void cp_async16(uint32_t saddr, const void* g) {
    asm volatile("cp.async.cg.shared.global [%0], [%1], 16;"
                 :: "r"(saddr), "l"(g) : "memory");
}
#define CP_COMMIT() asm volatile("cp.async.commit_group;" ::: "memory")
#define CP_WAIT1()  asm volatile("cp.async.wait_group 1;" ::: "memory")

__device__ __forceinline__ void ldm_x4(uint32_t* r, uint32_t addr) {
    asm volatile("ldmatrix.sync.aligned.m8n8.x4.shared.b16 {%0,%1,%2,%3}, [%4];"
                 : "=r"(r[0]), "=r"(r[1]), "=r"(r[2]), "=r"(r[3]) : "r"(addr));
}
__device__ __forceinline__ void mma_bf16(float* d, const uint32_t* a, const uint32_t* b) {
    asm volatile("mma.sync.aligned.m16n8k16.row.col.f32.bf16.bf16.f32 "
                 "{%0,%1,%2,%3}, {%4,%5,%6,%7}, {%8,%9}, {%0,%1,%2,%3};"
                 : "+f"(d[0]), "+f"(d[1]), "+f"(d[2]), "+f"(d[3])
                 : "r"(a[0]), "r"(a[1]), "r"(a[2]), "r"(a[3]),
                   "r"(b[0]), "r"(b[1]));
}

// ---------------- fused: GroupNorm stats (blocks 0..63) + prep (64..127) ------
__global__ void prep_stats(const float* __restrict__ x, float* __restrict__ stats,
                           const float* __restrict__ wq, const float* __restrict__ wk,
                           const float* __restrict__ wv, const float* __restrict__ wo,
                           const float* __restrict__ bq, const float* __restrict__ bk,
                           __nv_bfloat16* __restrict__ wb, float* __restrict__ bqk,
                           float* __restrict__ rowsum)
{
    const int tid = threadIdx.x;
    if (blockIdx.x < BATCH * NGROUPS) {
        const int bg = blockIdx.x;
        const size_t base = (size_t)bg * CPG * HW;
        const float4* xv = (const float4*)(x + base);
        const int NV = CPG * HW / 4;

        float s = 0.f, ss = 0.f;
        for (int i = tid; i < NV; i += 256) {
            float4 v = xv[i];
            s  += v.x + v.y + v.z + v.w;
            ss += v.x * v.x + v.y * v.y + v.z * v.z + v.w * v.w;
        }
        __shared__ float r1[256], r2[256];
        r1[tid] = s; r2[tid] = ss;
        __syncthreads();
        for (int o = 128; o > 0; o >>= 1) {
            if (tid < o) { r1[tid] += r1[tid + o]; r2[tid] += r2[tid + o]; }
            __syncthreads();
        }
        if (tid == 0) {
            const float inv_n = 1.0f / (float)(CPG * HW);
            float mu  = r1[0] * inv_n;
            float var = r2[0] * inv_n - mu * mu;
            stats[bg * 2 + 0] = mu;
            stats[bg * 2 + 1] = rsqrtf(var + EPS);
        }
    } else {
        const int CC = C_DIM * C_DIM;
        const int pid = (blockIdx.x - BATCH * NGROUPS) * 256 + tid;
        const int nt = 64 * 256;
        __nv_bfloat162* w2 = (__nv_bfloat162*)wb;
        for (int j = pid; j < CC / 2; j += nt) {
            float2 a;
            a = ((const float2*)wq)[j]; w2[j]          = __floats2bfloat162_rn(a.x, a.y);
            a = ((const float2*)wk)[j]; w2[CC/2 + j]   = __floats2bfloat162_rn(a.x, a.y);
            a = ((const float2*)wv)[j]; w2[CC + j]     = __floats2bfloat162_rn(a.x, a.y);
            a = ((const float2*)wo)[j]; w2[3*CC/2 + j] = __floats2bfloat162_rn(a.x, a.y);
        }
        if (pid < C_DIM) { bqk[pid] = bq[pid]; bqk[C_DIM + pid] = bk[pid]; }
        for (int j = pid; j < BATCH * HW; j += nt) rowsum[j] = 0.f;
    }
}

// ---------------- GroupNorm apply + transpose to (n, c) bf16 ------------------
__global__ void gn_apply_t(const float* __restrict__ x,
                           const float* __restrict__ gamma,
                           const float* __restrict__ beta,
                           const float* __restrict__ stats,
                           __nv_bfloat16* __restrict__ hT)
{
    __shared__ float s[64][65];
    const int b  = blockIdx.z;
    const int c0 = blockIdx.y * 64;
    const int n0 = blockIdx.x * 64;
    const int t  = threadIdx.x;
    const int j  = t & 63;
    const int i4 = t >> 6;

#pragma unroll 4
    for (int r = 0; r < 16; r++) {
        const int cl = i4 * 16 + r;
        const int c  = c0 + cl;
        const int g  = c >> 4;
        const float mu   = stats[(b * NGROUPS + g) * 2 + 0];
        const float rinv = stats[(b * NGROUPS + g) * 2 + 1];
        const float ga = gamma[c] * rinv;
        const float be = beta[c] - mu * ga;
        float v = x[((size_t)b * C_DIM + c) * HW + n0 + j];
        s[cl][j] = v * ga + be;
    }
    __syncthreads();
#pragma unroll 4
    for (int r = 0; r < 16; r++) {
        const int nl = i4 * 16 + r;
        hT[((size_t)b * HW + n0 + nl) * C_DIM + c0 + j] = __float2bfloat16(s[j][nl]);
    }
}

// ---------------- bf16 mma.sync GEMM ------------------------------------------
// D(m,n) = epi( sum_k A(m,k) * B(n,k) ); A: rows of ldA, B: rows of ldB.
// Block 128x128, k-tile 64, 3-stage cp.async pipeline, one barrier per chunk.
enum { E_QK = 0, E_V = 1, E_EXP = 2, E_AV = 3, E_FIN = 4 };

#define TILE_BYTES 16384           // 128 rows x 128 bytes
#define NSTAGE 3
#define SMEM_BYTES (2 * NSTAGE * TILE_BYTES)   // 96 KB -> 2 CTA/SM

__device__ __forceinline__ void load_tile_async(const __nv_bfloat16* __restrict__ g,
                                                int row0, int k0, int ld,
                                                uint32_t sdst, int t)
{
    const char* base = (const char*)(g + (size_t)row0 * ld + k0);
#pragma unroll
    for (int i = 0; i < 4; i++) {
        int idx = i * 256 + t;          // 0..1023
        int r   = idx >> 3;             // 0..127
        int c16 = idx & 7;              // 16B chunk within the 128B row
        const char* src = base + (size_t)r * ld * 2 + c16 * 16;
        uint32_t so = SMEM_SWIZZLE_128B((uint32_t)(r * 128 + c16 * 16));
        cp_async16(sdst + so, src);
    }
}

template<int EPI>
__global__ void __launch_bounds__(256, 2) gemm_mma(
    const __nv_bfloat16* __restrict__ A, const __nv_bfloat16* __restrict__ B,
    void* __restrict__ Cv, const float* __restrict__ bias,
    float* __restrict__ rowsum, const float* __restrict__ resid,
    int M, int N, int K, int ldA, int ldB,
    long sA, long sB, long sC, float alpha)
{
    extern __shared__ char smem[];
    const uint32_t sb = smem_u32(smem);
    const int t = threadIdx.x, lane = t & 31, wid = t >> 5;
    const int wm = wid >> 2;            // 0..1 : 64-row slab
    const int wn = wid & 3;             // 0..3 : 32-col slab
    const int bz = blockIdx.z;
    A += (size_t)bz * sA;
    B += (size_t)bz * sB;
    if (EPI == E_EXP || EPI == E_AV) rowsum += (size_t)bz * HW;
    const int m0 = blockIdx.y * 128;
    const int n0 = blockIdx.x * 128;

    float acc[4][4][4] = {};

    const int NC = K >> 6;
    // prologue: stages 0 and 1 in flight
    load_tile_async(A, m0, 0, ldA, sb, t);
    load_tile_async(B, n0, 0, ldB, sb + NSTAGE * TILE_BYTES, t);
    CP_COMMIT();
    load_tile_async(A, m0, 64, ldA, sb + TILE_BYTES, t);
    load_tile_async(B, n0, 64, ldB, sb + (NSTAGE + 1) * TILE_BYTES, t);
    CP_COMMIT();

    // lane-constant address components
    const uint32_t a_r = (uint32_t)(wm * 64 + (lane & 15));
    const uint32_t a_c = (uint32_t)((lane >> 4) * 16);          // bytes
    const uint32_t b_r = (uint32_t)(wn * 32 + (lane & 7) + ((lane >> 4) & 1) * 8);
    const uint32_t b_c = (uint32_t)(((lane >> 3) & 1) * 16);    // bytes

    for (int c = 0; c < NC; c++) {
        CP_WAIT1();
        __syncthreads();

        // issue loads for stage c+2 AFTER the barrier (slot last read at iter c-1)
        if (c + 2 < NC) {
            const int st = (c + 2) % NSTAGE;
            load_tile_async(A, m0, (c + 2) * 64, ldA, sb + st * TILE_BYTES, t);
            load_tile_async(B, n0, (c + 2) * 64, ldB, sb + (NSTAGE + st) * TILE_BYTES, t);
        }
        CP_COMMIT();   // commit every iter (possibly empty) to keep accounting aligned

        const uint32_t abuf = sb + (c % NSTAGE) * TILE_BYTES;
        const uint32_t bbuf = sb + (NSTAGE + c % NSTAGE) * TILE_BYTES;
#pragma unroll
        for (int ks = 0; ks < 4; ks++) {
            uint32_t af[4][4];
#pragma unroll
            for (int tm = 0; tm < 4; tm++) {
                uint32_t off = (a_r + tm * 16) * 128 + (uint32_t)(ks * 32) + a_c;
                ldm_x4(af[tm], abuf + SMEM_SWIZZLE_128B(off));
            }
            uint32_t bf[4][2];
#pragma unroll
            for (int p = 0; p < 2; p++) {
                uint32_t r4[4];
                uint32_t off = (b_r + p * 16) * 128 + (uint32_t)(ks * 32) + b_c;
                ldm_x4(r4, bbuf + SMEM_SWIZZLE_128B(off));
                bf[2 * p][0] = r4[0]; bf[2 * p][1] = r4[1];
                bf[2 * p + 1][0] = r4[2]; bf[2 * p + 1][1] = r4[3];
            }
#pragma unroll
            for (int tm = 0; tm < 4; tm++)
#pragma unroll
                for (int tn = 0; tn < 4; tn++)
                    mma_bf16(acc[tm][tn], af[tm], bf[tn]);
        }
    }

    // ---------------- epilogue ----------------
    const int gq = lane >> 2, tq = lane & 3;
#pragma unroll
    for (int tm = 0; tm < 4; tm++) {
#pragma unroll
        for (int h = 0; h < 2; h++) {
            const int m = m0 + wm * 64 + tm * 16 + gq + h * 8;
            float rowadd = 0.f;
            float pm = 0.f;
            if (EPI == E_V || EPI == E_FIN) pm = bias[m];
            if (EPI == E_AV) pm = 1.0f / rowsum[m];
#pragma unroll
            for (int tn = 0; tn < 4; tn++) {
                const int n = n0 + wn * 32 + tn * 8 + tq * 2;
                float d0 = acc[tm][tn][h * 2 + 0];
                float d1 = acc[tm][tn][h * 2 + 1];
                if (EPI == E_QK) { d0 += bias[n]; d1 += bias[n + 1]; }
                if (EPI == E_V)  { d0 += pm; d1 += pm; }
                if (EPI == E_EXP) {
                    d0 = __expf(d0 * alpha);
                    d1 = __expf(d1 * alpha);
                    rowadd += d0 + d1;
                }
                if (EPI == E_AV) { d0 *= pm; d1 *= pm; }
                if (EPI == E_FIN) {
                    const float2 rr = *(const float2*)(resid + (size_t)bz * sC + (size_t)m * N + n);
                    float2 o = make_float2(d0 + pm + rr.x, d1 + pm + rr.y);
                    *(float2*)((float*)Cv + (size_t)bz * sC + (size_t)m * N + n) = o;
                } else {
                    __nv_bfloat162 p2 = __floats2bfloat162_rn(d0, d1);
                    *(__nv_bfloat162*)((__nv_bfloat16*)Cv + (size_t)bz * sC + (size_t)m * N + n) = p2;
                }
            }
            if (EPI == E_EXP) {
                rowadd += __shfl_xor_sync(0xffffffff, rowadd, 1);
                rowadd += __shfl_xor_sync(0xffffffff, rowadd, 2);
                if (tq == 0) atomicAdd(&rowsum[m], rowadd);
            }
        }
    }
}

// ---------------- launch -------------------------------------------------------
extern "C" void kernel_launch(void* const* d_in, const int* in_sizes, int n_in,
                              void* d_out, int out_size)
{
    const float* x    = (const float*)d_in[0];
    const float* gn_w = (const float*)d_in[1];
    const float* gn_b = (const float*)d_in[2];
    const float* wq   = (const float*)d_in[3];
    const float* bq   = (const float*)d_in[4];
    const float* wk   = (const float*)d_in[5];
    const float* bk   = (const float*)d_in[6];
    const float* wv   = (const float*)d_in[7];
    const float* bv   = (const float*)d_in[8];
    const float* wo   = (const float*)d_in[9];
    const float* bo   = (const float*)d_in[10];
    float* out = (float*)d_out;

    __nv_bfloat16 *hT, *qkT, *v, *oT, *es, *wb;
    float *rowsum, *stats, *bqk;
    cudaGetSymbolAddress((void**)&hT,  g_hT);
    cudaGetSymbolAddress((void**)&qkT, g_qkT);
    cudaGetSymbolAddress((void**)&v,   g_v);
    cudaGetSymbolAddress((void**)&oT,  g_oT);
    cudaGetSymbolAddress((void**)&es,  g_es);
    cudaGetSymbolAddress((void**)&wb,  g_wb);
    cudaGetSymbolAddress((void**)&rowsum, g_rowsum);
    cudaGetSymbolAddress((void**)&stats,  g_stats);
    cudaGetSymbolAddress((void**)&bqk,    g_bqk);

    cudaFuncSetAttribute(gemm_mma<E_QK>,  cudaFuncAttributeMaxDynamicSharedMemorySize, SMEM_BYTES);
    cudaFuncSetAttribute(gemm_mma<E_V>,   cudaFuncAttributeMaxDynamicSharedMemorySize, SMEM_BYTES);
    cudaFuncSetAttribute(gemm_mma<E_EXP>, cudaFuncAttributeMaxDynamicSharedMemorySize, SMEM_BYTES);
    cudaFuncSetAttribute(gemm_mma<E_AV>,  cudaFuncAttributeMaxDynamicSharedMemorySize, SMEM_BYTES);
    cudaFuncSetAttribute(gemm_mma<E_FIN>, cudaFuncAttributeMaxDynamicSharedMemorySize, SMEM_BYTES);

    // one-time side stream + events for the E_V fork (no device allocations)
    static cudaStream_t s1 = nullptr;
    static cudaEvent_t evFork = nullptr, evJoin = nullptr;
    if (s1 == nullptr) {
        cudaStreamCreateWithFlags(&s1, cudaStreamNonBlocking);
        cudaEventCreateWithFlags(&evFork, cudaEventDisableTiming);
        cudaEventCreateWithFlags(&evJoin, cudaEventDisableTiming);
    }

    const long NC_  = (long)HW * C_DIM;        // hT / v / oT per-batch stride
    const long NC2_ = (long)HW * 2 * C_DIM;    // qkT per-batch stride
    const long CN_  = (long)C_DIM * HW;
    const long NN_  = (long)HW * HW;
    const int  CC   = C_DIM * C_DIM;
    const float scale = 0.044194173824159216f; // 512^-0.5

    // fused GroupNorm stats + weight/bias/rowsum prep, then GN apply -> hT
    prep_stats<<<128, 256>>>(x, stats, wq, wk, wv, wo, bq, bk, wb, bqk, rowsum);
    gn_apply_t<<<dim3(HW / 64, C_DIM / 64, BATCH), 256>>>(x, gn_w, gn_b, stats, hT);

    // fork: E_V on side stream (needs wb + hT, both ready here); overlaps E_QK/E_EXP
    cudaEventRecord(evFork, 0);
    cudaStreamWaitEvent(s1, evFork, 0);
    gemm_mma<E_V><<<dim3(32, 4, BATCH), 256, SMEM_BYTES, s1>>>(
        wb + 2 * CC, hT, v, bv, nullptr, nullptr,
        C_DIM, HW, C_DIM, C_DIM, C_DIM, 0, NC_, CN_, 0.f);
    cudaEventRecord(evJoin, s1);

    // qkT(n, 0:1024) = hT(n,:) . [Wq;Wk](c,:) + bqk[c]   (M=HW, N=1024, K=512)
    gemm_mma<E_QK><<<dim3(8, 32, BATCH), 256, SMEM_BYTES>>>(
        hT, wb, qkT, bqk, nullptr, nullptr,
        HW, 2 * C_DIM, C_DIM, C_DIM, C_DIM, NC_, 0, NC2_, 0.f);

    // es(nq,nk) = exp(q(nq,:) . k(nk,:) * scale); rowsum accumulated
    gemm_mma<E_EXP><<<dim3(32, 32, BATCH), 256, SMEM_BYTES>>>(
        qkT, qkT + C_DIM, es, nullptr, rowsum, nullptr,
        HW, HW, C_DIM, 2 * C_DIM, 2 * C_DIM, NC2_, NC2_, NN_, scale);

    // join: E_AV needs v from the side stream
    cudaStreamWaitEvent(0, evJoin, 0);

    // oT(nq,c) = (es(nq,:) . v(c,:)) / rowsum[nq]   (M=HW, N=C, K=HW)
    gemm_mma<E_AV><<<dim3(4, 32, BATCH), 256, SMEM_BYTES>>>(
        es, v, oT, nullptr, rowsum, nullptr,
        HW, C_DIM, HW, HW, HW, NN_, CN_, NC_, 0.f);

    // out(c,n) = Wo(c,:) . oT(n,:) + bo[c] + x(c,n)   (M=C, N=HW, K=C)
    gemm_mma<E_FIN><<<dim3(32, 4, BATCH), 256, SMEM_BYTES>>>(
        wb + 3 * CC, oT, out, bo, nullptr, x,
        C_DIM, HW, C_DIM, C_DIM, C_DIM, 0, NC_, CN_, 0.f);
}

// round 15
// speedup vs baseline: 1.0585x; 1.0208x over previous
#include <cuda_runtime.h>
#include <cuda_bf16.h>
#include <cstdint>
#include <math.h>

#define C_DIM   512
#define HW      4096
#define BATCH   2
#define NGROUPS 32
#define CPG     16
#define EPS     1e-5f

// ---------------- scratch (device globals; allocations forbidden) -----------
__device__ __align__(16) __nv_bfloat16 g_hT [(size_t)BATCH * HW * C_DIM];      // (b, n, c)
__device__ __align__(16) __nv_bfloat16 g_qkT[(size_t)BATCH * HW * 2 * C_DIM];  // (b, n, 1024) q|k
__device__ __align__(16) __nv_bfloat16 g_v  [(size_t)BATCH * C_DIM * HW];      // (b, c, n)
__device__ __align__(16) __nv_bfloat16 g_oT [(size_t)BATCH * HW * C_DIM];      // (b, n, c)
__device__ __align__(16) __nv_bfloat16 g_es [(size_t)BATCH * HW * HW];         // exp(scores)
__device__ __align__(16) __nv_bfloat16 g_wb [4 * C_DIM * C_DIM];               // bf16 weights
__device__ float g_bqk[2 * C_DIM];
__device__ float g_rowsum[BATCH * HW];
__device__ float g_stats[BATCH * NGROUPS * 2];

// ---------------- helpers ----------------------------------------------------
__device__ __forceinline__ uint32_t smem_u32(const void* p) {
    uint32_t a;
    asm("{ .reg .u64 t; cvta.to.shared.u64 t, %1; cvt.u32.u64 %0, t; }"
        : "=r"(a) : "l"(p));
    return a;
}
#define SMEM_SWIZZLE_128B(off) ((off) ^ (((off) >> 3) & 0x70))

__device__ __forceinline__ void cp_async16(uint32_t saddr, const void* g) {
    asm volatile("cp.async.cg.shared.global [%0], [%1], 16;"
                 :: "r"(saddr), "l"(g) : "memory");
}
#define CP_COMMIT() asm volatile("cp.async.commit_group;" ::: "memory")
#define CP_WAIT1()  asm volatile("cp.async.wait_group 1;" ::: "memory")

__device__ __forceinline__ void ldm_x4(uint32_t* r, uint32_t addr) {
    asm volatile("ldmatrix.sync.aligned.m8n8.x4.shared.b16 {%0,%1,%2,%3}, [%4];"
                 : "=r"(r[0]), "=r"(r[1]), "=r"(r[2]), "=r"(r[3]) : "r"(addr));
}
__device__ __forceinline__ void mma_bf16(float* d, const uint32_t* a, const uint32_t* b) {
    asm volatile("mma.sync.aligned.m16n8k16.row.col.f32.bf16.bf16.f32 "
                 "{%0,%1,%2,%3}, {%4,%5,%6,%7}, {%8,%9}, {%0,%1,%2,%3};"
                 : "+f"(d[0]), "+f"(d[1]), "+f"(d[2]), "+f"(d[3])
                 : "r"(a[0]), "r"(a[1]), "r"(a[2]), "r"(a[3]),
                   "r"(b[0]), "r"(b[1]));
}

// ---------------- fused: GroupNorm stats (blocks 0..63) + prep (64..127) ------
__global__ void prep_stats(const float* __restrict__ x, float* __restrict__ stats,
                           const float* __restrict__ wq, const float* __restrict__ wk,
                           const float* __restrict__ wv, const float* __restrict__ wo,
                           const float* __restrict__ bq, const float* __restrict__ bk,
                           __nv_bfloat16* __restrict__ wb, float* __restrict__ bqk,
                           float* __restrict__ rowsum)
{
    const int tid = threadIdx.x;
    if (blockIdx.x < BATCH * NGROUPS) {
        const int bg = blockIdx.x;
        const size_t base = (size_t)bg * CPG * HW;
        const float4* xv = (const float4*)(x + base);
        const int NV = CPG * HW / 4;

        float s = 0.f, ss = 0.f;
        for (int i = tid; i < NV; i += 256) {
            float4 v = xv[i];
            s  += v.x + v.y + v.z + v.w;
            ss += v.x * v.x + v.y * v.y + v.z * v.z + v.w * v.w;
        }
        __shared__ float r1[256], r2[256];
        r1[tid] = s; r2[tid] = ss;
        __syncthreads();
        for (int o = 128; o > 0; o >>= 1) {
            if (tid < o) { r1[tid] += r1[tid + o]; r2[tid] += r2[tid + o]; }
            __syncthreads();
        }
        if (tid == 0) {
            const float inv_n = 1.0f / (float)(CPG * HW);
            float mu  = r1[0] * inv_n;
            float var = r2[0] * inv_n - mu * mu;
            stats[bg * 2 + 0] = mu;
            stats[bg * 2 + 1] = rsqrtf(var + EPS);
        }
    } else {
        const int CC = C_DIM * C_DIM;
        const int pid = (blockIdx.x - BATCH * NGROUPS) * 256 + tid;
        const int nt = 64 * 256;
        __nv_bfloat162* w2 = (__nv_bfloat162*)wb;
        for (int j = pid; j < CC / 2; j += nt) {
            float2 a;
            a = ((const float2*)wq)[j]; w2[j]          = __floats2bfloat162_rn(a.x, a.y);
            a = ((const float2*)wk)[j]; w2[CC/2 + j]   = __floats2bfloat162_rn(a.x, a.y);
            a = ((const float2*)wv)[j]; w2[CC + j]     = __floats2bfloat162_rn(a.x, a.y);
            a = ((const float2*)wo)[j]; w2[3*CC/2 + j] = __floats2bfloat162_rn(a.x, a.y);
        }
        if (pid < C_DIM) { bqk[pid] = bq[pid]; bqk[C_DIM + pid] = bk[pid]; }
        for (int j = pid; j < BATCH * HW; j += nt) rowsum[j] = 0.f;
    }
}

// ---------------- GroupNorm apply + transpose to (n, c) bf16 ------------------
__global__ void gn_apply_t(const float* __restrict__ x,
                           const float* __restrict__ gamma,
                           const float* __restrict__ beta,
                           const float* __restrict__ stats,
                           __nv_bfloat16* __restrict__ hT)
{
    __shared__ float s[64][65];
    const int b  = blockIdx.z;
    const int c0 = blockIdx.y * 64;
    const int n0 = blockIdx.x * 64;
    const int t  = threadIdx.x;
    const int j  = t & 63;
    const int i4 = t >> 6;

#pragma unroll 4
    for (int r = 0; r < 16; r++) {
        const int cl = i4 * 16 + r;
        const int c  = c0 + cl;
        const int g  = c >> 4;
        const float mu   = stats[(b * NGROUPS + g) * 2 + 0];
        const float rinv = stats[(b * NGROUPS + g) * 2 + 1];
        const float ga = gamma[c] * rinv;
        const float be = beta[c] - mu * ga;
        float v = x[((size_t)b * C_DIM + c) * HW + n0 + j];
        s[cl][j] = v * ga + be;
    }
    __syncthreads();
#pragma unroll 4
    for (int r = 0; r < 16; r++) {
        const int nl = i4 * 16 + r;
        hT[((size_t)b * HW + n0 + nl) * C_DIM + c0 + j] = __float2bfloat16(s[j][nl]);
    }
}

// ---------------- bf16 mma.sync GEMM ------------------------------------------
// D(m,n) = epi( sum_k A(m,k) * B(n,k) ); A: rows of ldA, B: rows of ldB.
// Block 128x128, k-tile 64, 3-stage cp.async pipeline, one barrier per chunk.
enum { E_QK = 0, E_V = 1, E_EXP = 2, E_AV = 3, E_FIN = 4 };

#define TILE_BYTES 16384           // 128 rows x 128 bytes
#define NSTAGE 3
#define SMEM_BYTES (2 * NSTAGE * TILE_BYTES)   // 96 KB -> 2 CTA/SM

__device__ __forceinline__ void load_tile_async(const __nv_bfloat16* __restrict__ g,
                                                int row0, int k0, int ld,
                                                uint32_t sdst, int t)
{
    const char* base = (const char*)(g + (size_t)row0 * ld + k0);
#pragma unroll
    for (int i = 0; i < 4; i++) {
        int idx = i * 256 + t;          // 0..1023
        int r   = idx >> 3;             // 0..127
        int c16 = idx & 7;              // 16B chunk within the 128B row
        const char* src = base + (size_t)r * ld * 2 + c16 * 16;
        uint32_t so = SMEM_SWIZZLE_128B((uint32_t)(r * 128 + c16 * 16));
        cp_async16(sdst + so, src);
    }
}

template<int EPI>
__global__ void __launch_bounds__(256, 2) gemm_mma(
    const __nv_bfloat16* __restrict__ A, const __nv_bfloat16* __restrict__ B,
    void* __restrict__ Cv, const float* __restrict__ bias,
    float* __restrict__ rowsum, const float* __restrict__ resid,
    int M, int N, int K, int ldA, int ldB,
    long sA, long sB, long sC, float alpha)
{
    extern __shared__ char smem[];
    const uint32_t sb = smem_u32(smem);
    const int t = threadIdx.x, lane = t & 31, wid = t >> 5;
    const int wm = wid >> 2;            // 0..1 : 64-row slab
    const int wn = wid & 3;             // 0..3 : 32-col slab
    const int bz = blockIdx.z;
    A += (size_t)bz * sA;
    B += (size_t)bz * sB;
    if (EPI == E_EXP || EPI == E_AV) rowsum += (size_t)bz * HW;
    const int m0 = blockIdx.y * 128;
    const int n0 = blockIdx.x * 128;

    // PDL: wait for upstream kernel before any dependent global read
    cudaGridDependencySynchronize();

    float acc[4][4][4] = {};

    const int NC = K >> 6;
    // prologue: stages 0 and 1 in flight
    load_tile_async(A, m0, 0, ldA, sb, t);
    load_tile_async(B, n0, 0, ldB, sb + NSTAGE * TILE_BYTES, t);
    CP_COMMIT();
    load_tile_async(A, m0, 64, ldA, sb + TILE_BYTES, t);
    load_tile_async(B, n0, 64, ldB, sb + (NSTAGE + 1) * TILE_BYTES, t);
    CP_COMMIT();

    // lane-constant address components
    const uint32_t a_r = (uint32_t)(wm * 64 + (lane & 15));
    const uint32_t a_c = (uint32_t)((lane >> 4) * 16);          // bytes
    const uint32_t b_r = (uint32_t)(wn * 32 + (lane & 7) + ((lane >> 4) & 1) * 8);
    const uint32_t b_c = (uint32_t)(((lane >> 3) & 1) * 16);    // bytes

    for (int c = 0; c < NC; c++) {
        CP_WAIT1();
        __syncthreads();

        // issue loads for stage c+2 AFTER the barrier (slot last read at iter c-1)
        if (c + 2 < NC) {
            const int st = (c + 2) % NSTAGE;
            load_tile_async(A, m0, (c + 2) * 64, ldA, sb + st * TILE_BYTES, t);
            load_tile_async(B, n0, (c + 2) * 64, ldB, sb + (NSTAGE + st) * TILE_BYTES, t);
        }
        CP_COMMIT();   // commit every iter (possibly empty) to keep accounting aligned

        const uint32_t abuf = sb + (c % NSTAGE) * TILE_BYTES;
        const uint32_t bbuf = sb + (NSTAGE + c % NSTAGE) * TILE_BYTES;
#pragma unroll
        for (int ks = 0; ks < 4; ks++) {
            uint32_t af[4][4];
#pragma unroll
            for (int tm = 0; tm < 4; tm++) {
                uint32_t off = (a_r + tm * 16) * 128 + (uint32_t)(ks * 32) + a_c;
                ldm_x4(af[tm], abuf + SMEM_SWIZZLE_128B(off));
            }
            uint32_t bf[4][2];
#pragma unroll
            for (int p = 0; p < 2; p++) {
                uint32_t r4[4];
                uint32_t off = (b_r + p * 16) * 128 + (uint32_t)(ks * 32) + b_c;
                ldm_x4(r4, bbuf + SMEM_SWIZZLE_128B(off));
                bf[2 * p][0] = r4[0]; bf[2 * p][1] = r4[1];
                bf[2 * p + 1][0] = r4[2]; bf[2 * p + 1][1] = r4[3];
            }
#pragma unroll
            for (int tm = 0; tm < 4; tm++)
#pragma unroll
                for (int tn = 0; tn < 4; tn++)
                    mma_bf16(acc[tm][tn], af[tm], bf[tn]);
        }
    }

    // ---------------- epilogue ----------------
    const int gq = lane >> 2, tq = lane & 3;
#pragma unroll
    for (int tm = 0; tm < 4; tm++) {
#pragma unroll
        for (int h = 0; h < 2; h++) {
            const int m = m0 + wm * 64 + tm * 16 + gq + h * 8;
            float rowadd = 0.f;
            float pm = 0.f;
            if (EPI == E_V || EPI == E_FIN) pm = bias[m];
            if (EPI == E_AV) pm = 1.0f / rowsum[m];
#pragma unroll
            for (int tn = 0; tn < 4; tn++) {
                const int n = n0 + wn * 32 + tn * 8 + tq * 2;
                float d0 = acc[tm][tn][h * 2 + 0];
                float d1 = acc[tm][tn][h * 2 + 1];
                if (EPI == E_QK) { d0 += bias[n]; d1 += bias[n + 1]; }
                if (EPI == E_V)  { d0 += pm; d1 += pm; }
                if (EPI == E_EXP) {
                    d0 = __expf(d0 * alpha);
                    d1 = __expf(d1 * alpha);
                    rowadd += d0 + d1;
                }
                if (EPI == E_AV) { d0 *= pm; d1 *= pm; }
                if (EPI == E_FIN) {
                    const float2 rr = *(const float2*)(resid + (size_t)bz * sC + (size_t)m * N + n);
                    float2 o = make_float2(d0 + pm + rr.x, d1 + pm + rr.y);
                    *(float2*)((float*)Cv + (size_t)bz * sC + (size_t)m * N + n) = o;
                } else {
                    __nv_bfloat162 p2 = __floats2bfloat162_rn(d0, d1);
                    *(__nv_bfloat162*)((__nv_bfloat16*)Cv + (size_t)bz * sC + (size_t)m * N + n) = p2;
                }
            }
            if (EPI == E_EXP) {
                rowadd += __shfl_xor_sync(0xffffffff, rowadd, 1);
                rowadd += __shfl_xor_sync(0xffffffff, rowadd, 2);
                if (tq == 0) atomicAdd(&rowsum[m], rowadd);
            }
        }
    }
}

// ---------------- PDL launch helper -------------------------------------------
template<int EPI>
static void launch_pdl(dim3 grid,
                       const __nv_bfloat16* A, const __nv_bfloat16* B,
                       void* Cv, const float* bias, float* rowsum,
                       const float* resid,
                       int M, int N, int K, int ldA, int ldB,
                       long sA, long sB, long sC, float alpha)
{
    cudaLaunchConfig_t cfg = {};
    cfg.gridDim = grid;
    cfg.blockDim = dim3(256, 1, 1);
    cfg.dynamicSmemBytes = SMEM_BYTES;
    cfg.stream = 0;
    cudaLaunchAttribute at[1];
    at[0].id = cudaLaunchAttributeProgrammaticStreamSerialization;
    at[0].val.programmaticStreamSerializationAllowed = 1;
    cfg.attrs = at;
    cfg.numAttrs = 1;
    cudaLaunchKernelEx(&cfg, gemm_mma<EPI>, A, B, Cv, bias, rowsum, resid,
                       M, N, K, ldA, ldB, sA, sB, sC, alpha);
}

// ---------------- launch -------------------------------------------------------
extern "C" void kernel_launch(void* const* d_in, const int* in_sizes, int n_in,
                              void* d_out, int out_size)
{
    const float* x    = (const float*)d_in[0];
    const float* gn_w = (const float*)d_in[1];
    const float* gn_b = (const float*)d_in[2];
    const float* wq   = (const float*)d_in[3];
    const float* bq   = (const float*)d_in[4];
    const float* wk   = (const float*)d_in[5];
    const float* bk   = (const float*)d_in[6];
    const float* wv   = (const float*)d_in[7];
    const float* bv   = (const float*)d_in[8];
    const float* wo   = (const float*)d_in[9];
    const float* bo   = (const float*)d_in[10];
    float* out = (float*)d_out;

    __nv_bfloat16 *hT, *qkT, *v, *oT, *es, *wb;
    float *rowsum, *stats, *bqk;
    cudaGetSymbolAddress((void**)&hT,  g_hT);
    cudaGetSymbolAddress((void**)&qkT, g_qkT);
    cudaGetSymbolAddress((void**)&v,   g_v);
    cudaGetSymbolAddress((void**)&oT,  g_oT);
    cudaGetSymbolAddress((void**)&es,  g_es);
    cudaGetSymbolAddress((void**)&wb,  g_wb);
    cudaGetSymbolAddress((void**)&rowsum, g_rowsum);
    cudaGetSymbolAddress((void**)&stats,  g_stats);
    cudaGetSymbolAddress((void**)&bqk,    g_bqk);

    cudaFuncSetAttribute(gemm_mma<E_QK>,  cudaFuncAttributeMaxDynamicSharedMemorySize, SMEM_BYTES);
    cudaFuncSetAttribute(gemm_mma<E_V>,   cudaFuncAttributeMaxDynamicSharedMemorySize, SMEM_BYTES);
    cudaFuncSetAttribute(gemm_mma<E_EXP>, cudaFuncAttributeMaxDynamicSharedMemorySize, SMEM_BYTES);
    cudaFuncSetAttribute(gemm_mma<E_AV>,  cudaFuncAttributeMaxDynamicSharedMemorySize, SMEM_BYTES);
    cudaFuncSetAttribute(gemm_mma<E_FIN>, cudaFuncAttributeMaxDynamicSharedMemorySize, SMEM_BYTES);

    const long NC_  = (long)HW * C_DIM;        // hT / v / oT per-batch stride
    const long NC2_ = (long)HW * 2 * C_DIM;    // qkT per-batch stride
    const long CN_  = (long)C_DIM * HW;
    const long NN_  = (long)HW * HW;
    const int  CC   = C_DIM * C_DIM;
    const float scale = 0.044194173824159216f; // 512^-0.5

    // fused GroupNorm stats + weight/bias/rowsum prep, then GN apply -> hT
    prep_stats<<<128, 256>>>(x, stats, wq, wk, wv, wo, bq, bk, wb, bqk, rowsum);
    gn_apply_t<<<dim3(HW / 64, C_DIM / 64, BATCH), 256>>>(x, gn_w, gn_b, stats, hT);

    // qkT(n, 0:1024) = hT(n,:) . [Wq;Wk](c,:) + bqk[c]   (M=HW, N=1024, K=512)
    launch_pdl<E_QK>(dim3(8, 32, BATCH),
        hT, wb, qkT, bqk, nullptr, nullptr,
        HW, 2 * C_DIM, C_DIM, C_DIM, C_DIM, NC_, 0, NC2_, 0.f);

    // v(c,n) = Wv(c,:) . hT(n,:) + bv[c]   (M=C, N=HW, K=C)
    launch_pdl<E_V>(dim3(32, 4, BATCH),
        wb + 2 * CC, hT, v, bv, nullptr, nullptr,
        C_DIM, HW, C_DIM, C_DIM, C_DIM, 0, NC_, CN_, 0.f);

    // es(nq,nk) = exp(q(nq,:) . k(nk,:) * scale); rowsum accumulated
    launch_pdl<E_EXP>(dim3(32, 32, BATCH),
        qkT, qkT + C_DIM, es, nullptr, rowsum, nullptr,
        HW, HW, C_DIM, 2 * C_DIM, 2 * C_DIM, NC2_, NC2_, NN_, scale);

    // oT(nq,c) = (es(nq,:) . v(c,:)) / rowsum[nq]   (M=HW, N=C, K=HW)
    launch_pdl<E_AV>(dim3(4, 32, BATCH),
        es, v, oT, nullptr, rowsum, nullptr,
        HW, C_DIM, HW, HW, HW, NN_, CN_, NC_, 0.f);

    // out(c,n) = Wo(c,:) . oT(n,:) + bo[c] + x(c,n)   (M=C, N=HW, K=C)
    launch_pdl<E_FIN>(dim3(32, 4, BATCH),
        wb + 3 * CC, oT, out, bo, nullptr, x,
        C_DIM, HW, C_DIM, C_DIM, C_DIM, 0, NC_, CN_, 0.f);
}